// round 11
// baseline (speedup 1.0000x reference)
#include <cuda_runtime.h>
#include <cuda_fp16.h>
#include <math.h>
#include <stdint.h>

// Problem constants
#define MROWS  4096      // B*T
#define DMODEL 1024
#define D3     3072
#define DFF    4096
#define TSEQ   2048
#define NHEAD  16
#define DHEAD  64

// ---------------- scratch (device globals: no runtime allocation) ----------
__device__ float g_x1 [(size_t)MROWS * DMODEL];
__device__ __align__(16) __half g_qkv_h[(size_t)MROWS * D3];
__device__ __align__(16) __half g_xln_h[(size_t)MROWS * DMODEL];
__device__ __align__(16) __half g_y_h  [(size_t)MROWS * DMODEL];
__device__ __align__(16) __half g_h_h  [(size_t)MROWS * DMODEL];
__device__ __align__(16) __half g_act_h[(size_t)MROWS * DFF];
__device__ __align__(16) __half g_wq_h [(size_t)D3 * DMODEL];
__device__ __align__(16) __half g_wo_h [(size_t)DMODEL * DMODEL];
__device__ __align__(16) __half g_w1_h [(size_t)DFF * DMODEL];
__device__ __align__(16) __half g_w2_h [(size_t)DMODEL * DFF];

// ---------------- helpers ---------------------------------------------------
__device__ __forceinline__ uint32_t smem_u32(const void* p) {
    uint32_t a;
    asm("{ .reg .u64 t; cvta.to.shared.u64 t, %1; cvt.u32.u64 %0, t; }" : "=r"(a) : "l"(p));
    return a;
}
__device__ __forceinline__ void cpa16(uint32_t s, const void* g) {
    asm volatile("cp.async.cg.shared.global [%0], [%1], 16;" :: "r"(s), "l"(g));
}
__device__ __forceinline__ void cp_commit() { asm volatile("cp.async.commit_group;"); }
template <int N>
__device__ __forceinline__ void cp_wait() { asm volatile("cp.async.wait_group %0;" :: "n"(N)); }

__device__ __forceinline__ void ldsm4(uint32_t& r0, uint32_t& r1, uint32_t& r2, uint32_t& r3,
                                      uint32_t addr) {
    asm volatile("ldmatrix.sync.aligned.m8n8.x4.shared.b16 {%0,%1,%2,%3}, [%4];"
                 : "=r"(r0), "=r"(r1), "=r"(r2), "=r"(r3) : "r"(addr));
}
__device__ __forceinline__ void ldsm4t(uint32_t& r0, uint32_t& r1, uint32_t& r2, uint32_t& r3,
                                       uint32_t addr) {
    asm volatile("ldmatrix.sync.aligned.m8n8.x4.trans.shared.b16 {%0,%1,%2,%3}, [%4];"
                 : "=r"(r0), "=r"(r1), "=r"(r2), "=r"(r3) : "r"(addr));
}

__device__ __forceinline__ float gelu_exact(float v) {
    return 0.5f * v * (1.0f + erff(v * 0.70710678118654752f));
}

// mma.m16n8k16 fp16 -> fp32, row.col
__device__ __forceinline__ void mma16816(float* c, const uint32_t* a, const uint32_t* b) {
    asm volatile(
        "mma.sync.aligned.m16n8k16.row.col.f32.f16.f16.f32 "
        "{%0,%1,%2,%3}, {%4,%5,%6,%7}, {%8,%9}, {%0,%1,%2,%3};"
        : "+f"(c[0]), "+f"(c[1]), "+f"(c[2]), "+f"(c[3])
        : "r"(a[0]), "r"(a[1]), "r"(a[2]), "r"(a[3]), "r"(b[0]), "r"(b[1]));
}
__device__ __forceinline__ uint32_t pack_h2(float x, float y) {
    __half2 h = __floats2half2_rn(x, y);
    return *(uint32_t*)&h;
}

// ---------------- fused float -> half convert (4 arrays, grid.y selects) ----
__global__ void f2h4_kernel(const float4* s0, __half2* d0, int n0,
                            const float4* s1, __half2* d1, int n1,
                            const float4* s2, __half2* d2, int n2,
                            const float4* s3, __half2* d3, int n3) {
    const float4* src; __half2* dst; int n4;
    switch (blockIdx.y) {
        case 0: src = s0; dst = d0; n4 = n0; break;
        case 1: src = s1; dst = d1; n4 = n1; break;
        case 2: src = s2; dst = d2; n4 = n2; break;
        default: src = s3; dst = d3; n4 = n3; break;
    }
    int half_n = n4 >> 1;
    int i = blockIdx.x * blockDim.x + threadIdx.x;
    if (i < half_n) {
        float4 v0 = src[i];
        float4 v1 = src[i + half_n];
        dst[2 * i]     = __floats2half2_rn(v0.x, v0.y);
        dst[2 * i + 1] = __floats2half2_rn(v0.z, v0.w);
        dst[2 * (i + half_n)]     = __floats2half2_rn(v1.x, v1.y);
        dst[2 * (i + half_n) + 1] = __floats2half2_rn(v1.z, v1.w);
    }
}

// ---------------- LayerNorm (fp32 in, half out) -----------------------------
__global__ void ln_kernel(const float* __restrict__ x,
                          const float* __restrict__ w,
                          const float* __restrict__ b,
                          __half* __restrict__ out) {
    int row = blockIdx.x;
    int tid = threadIdx.x;
    const float* xr = x + (size_t)row * DMODEL;

    float4 v = *(const float4*)(xr + tid * 4);
    float s  = v.x + v.y + v.z + v.w;
    float ss = v.x * v.x + v.y * v.y + v.z * v.z + v.w * v.w;

    #pragma unroll
    for (int off = 16; off >= 1; off >>= 1) {
        s  += __shfl_xor_sync(0xffffffffu, s,  off);
        ss += __shfl_xor_sync(0xffffffffu, ss, off);
    }
    __shared__ float rs[8], rss[8];
    __shared__ float stats[2];
    int wid = tid >> 5, lane = tid & 31;
    if (lane == 0) { rs[wid] = s; rss[wid] = ss; }
    __syncthreads();
    if (tid == 0) {
        float S = 0.f, SS = 0.f;
        #pragma unroll
        for (int i = 0; i < 8; i++) { S += rs[i]; SS += rss[i]; }
        float mu  = S * (1.0f / DMODEL);
        float var = SS * (1.0f / DMODEL) - mu * mu;
        stats[0] = mu;
        stats[1] = rsqrtf(var + 1e-5f);
    }
    __syncthreads();
    float mu = stats[0], r = stats[1];

    float4 wv = *(const float4*)(w + tid * 4);
    float4 bv = *(const float4*)(b + tid * 4);
    float o0 = (v.x - mu) * r * wv.x + bv.x;
    float o1 = (v.y - mu) * r * wv.y + bv.y;
    float o2 = (v.z - mu) * r * wv.z + bv.z;
    float o3 = (v.w - mu) * r * wv.w + bv.w;
    __half2* orow = (__half2*)(out + (size_t)row * DMODEL);
    orow[tid * 2]     = __floats2half2_rn(o0, o1);
    orow[tid * 2 + 1] = __floats2half2_rn(o2, o3);
}

// ---------------- fp16 GEMM NT: ldmatrix + mma, swizzled smem ----------------
// (frozen — at the legacy-HMMA ceiling)
#define GK 64
#define NSTG 3
#define TILE_H (128 * 64)
#define STG_B (2 * TILE_H * 2)
#define GEMM_SMEM (NSTG * STG_B)          // 98304 bytes

__device__ __forceinline__ uint32_t swz(int row, int ch) {
    return (uint32_t)(row * 64 + ((ch ^ (row & 7)) * 8));
}

template <int EPI, int HOUT>
__global__ void __launch_bounds__(256, 2)
gemm_h(const __half* __restrict__ A, const __half* __restrict__ B,
       const float* __restrict__ bias, const float* __restrict__ res,
       float* __restrict__ C, __half* __restrict__ Ch, int N, int K) {
    extern __shared__ __align__(16) __half sm[];
    uint32_t sb = smem_u32(sm);

    int tid = threadIdx.x;
    int wid = tid >> 5, lane = tid & 31;
    int g = lane >> 2, t = lane & 3;
    int bn = blockIdx.x, bm = blockIdx.y;
    int wm = wid & 3;
    int wn = wid >> 2;
    const int KT = K / GK;

    float acc[2][8][4];
    #pragma unroll
    for (int mt = 0; mt < 2; mt++)
        #pragma unroll
        for (int n = 0; n < 8; n++)
            #pragma unroll
            for (int i = 0; i < 4; i++) acc[mt][n][i] = 0.f;

    const __half* Ab = A + (size_t)(bm * 128) * K;
    const __half* Bb = B + (size_t)(bn * 128) * K;

    auto issue = [&](int kt) {
        uint32_t dst = sb + (uint32_t)(kt % NSTG) * STG_B;
        #pragma unroll
        for (int i = 0; i < 4; i++) {
            int c = i * 256 + tid;
            int row = c >> 3, ch = c & 7;
            cpa16(dst + swz(row, ch) * 2,              Ab + (size_t)row * K + kt * GK + ch * 8);
            cpa16(dst + TILE_H * 2 + swz(row, ch) * 2, Bb + (size_t)row * K + kt * GK + ch * 8);
        }
    };

    issue(0); cp_commit();
    issue(1); cp_commit();

    for (int kt = 0; kt < KT; kt++) {
        bool more = (kt + 2 < KT);
        if (more) cp_wait<1>();
        else      cp_wait<0>();
        __syncthreads();
        if (more) { issue(kt + 2); cp_commit(); }

        uint32_t stA = sb + (uint32_t)(kt % NSTG) * STG_B;
        uint32_t stB = stA + TILE_H * 2;

        #pragma unroll
        for (int kk = 0; kk < 4; kk++) {
            uint32_t a[2][4];
            #pragma unroll
            for (int mt = 0; mt < 2; mt++) {
                int row = wm * 32 + mt * 16 + (lane & 7) + ((lane >> 3) & 1) * 8;
                int ch  = kk * 2 + (lane >> 4);
                ldsm4(a[mt][0], a[mt][1], a[mt][2], a[mt][3], stA + swz(row, ch) * 2);
            }
            uint32_t bfr[8][2];
            #pragma unroll
            for (int np = 0; np < 4; np++) {
                uint32_t r0, r1, r2, r3;
                int row = wn * 64 + np * 16 + (lane & 7) + ((lane >> 3) & 1) * 8;
                int ch  = kk * 2 + (lane >> 4);
                ldsm4(r0, r1, r2, r3, stB + swz(row, ch) * 2);
                bfr[np * 2][0]     = r0; bfr[np * 2][1]     = r2;
                bfr[np * 2 + 1][0] = r1; bfr[np * 2 + 1][1] = r3;
            }
            #pragma unroll
            for (int mt = 0; mt < 2; mt++)
                #pragma unroll
                for (int n = 0; n < 8; n++)
                    mma16816(acc[mt][n], a[mt], bfr[n]);
        }
    }

    __syncthreads();
    float* Cs = (float*)sm;
    #pragma unroll
    for (int mt = 0; mt < 2; mt++)
        #pragma unroll
        for (int n = 0; n < 8; n++) {
            int r0 = wm * 32 + mt * 16 + g;
            int c0 = wn * 64 + n * 8 + 2 * t;
            Cs[r0 * 132 + c0]           = acc[mt][n][0];
            Cs[r0 * 132 + c0 + 1]       = acc[mt][n][1];
            Cs[(r0 + 8) * 132 + c0]     = acc[mt][n][2];
            Cs[(r0 + 8) * 132 + c0 + 1] = acc[mt][n][3];
        }
    __syncthreads();

    int m0 = bm * 128, n0 = bn * 128;
    #pragma unroll
    for (int it = 0; it < 16; it++) {
        int idx = tid + it * 256;
        int r  = idx >> 5;
        int c4 = (idx & 31) * 4;
        float4 v = *(const float4*)&Cs[r * 132 + c4];
        float4 bv = *(const float4*)(bias + n0 + c4);
        v.x += bv.x; v.y += bv.y; v.z += bv.z; v.w += bv.w;
        if (EPI == 1) {
            v.x = gelu_exact(v.x); v.y = gelu_exact(v.y);
            v.z = gelu_exact(v.z); v.w = gelu_exact(v.w);
        }
        size_t off = (size_t)(m0 + r) * N + n0 + c4;
        if (EPI == 2) {
            float4 rv = *(const float4*)(res + off);
            v.x += rv.x; v.y += rv.y; v.z += rv.z; v.w += rv.w;
        }
        if (HOUT) {
            __half2* hp = (__half2*)(Ch + off);
            hp[0] = __floats2half2_rn(v.x, v.y);
            hp[1] = __floats2half2_rn(v.z, v.w);
        } else {
            *(float4*)(C + off) = v;
        }
    }
}

// ---------------- FA2 fp16 attention: Q-tile 128, 8 warps --------------------
// grid (T/128, H, B), 256 threads. K/V double-buffered cp.async (64-key blocks).
#define ATS 72    // smem stride in halves
#define ATT_SMEM ((128 * ATS + 4 * 64 * ATS) * 2)   // 55296 bytes (dynamic)

__global__ void __launch_bounds__(256)
attn_h(const __half* __restrict__ qkv, __half* __restrict__ y) {
    extern __shared__ __align__(16) __half smx[];
    __half* Qs = smx;                                  // [128][ATS]
    uint32_t sbKV = smem_u32(smx + 128 * ATS);         // [2 stages][K,V][64][ATS]

    int qb = blockIdx.x, h = blockIdx.y, b = blockIdx.z;
    int tid = threadIdx.x;
    int w = tid >> 5, lane = tid & 31;
    int g = lane >> 2, t = lane & 3;
    size_t base = (size_t)b * TSEQ * D3;
    int hoff = h * DHEAD;

    // stage load: K tile + V tile, 1024 x 16B chunks, 4 per thread
    auto loadKV = [&](int kb, int st) {
        #pragma unroll
        for (int i = 0; i < 4; i++) {
            int idx = tid + i * 256;            // 0..1023
            int isV = idx >> 9;                 // 0: K, 1: V
            int row = (idx >> 3) & 63;
            int ch  = idx & 7;
            const __half* src = qkv + base + (size_t)(kb * 64 + row) * D3 + hoff
                               + 1024 + isV * 1024 + ch * 8;
            cpa16(sbKV + (uint32_t)(((st * 2 + isV) * 64 + row) * ATS + ch * 8) * 2, src);
        }
    };

    // load Q tile [128 x 64] + prefetch KV(0)
    #pragma unroll
    for (int i = 0; i < 16; i++) {
        int idx = tid + i * 256;                // 0..4095 half2 slots
        int row = idx >> 5, c2 = idx & 31;
        *(__half2*)&Qs[row * ATS + c2 * 2] =
            *(const __half2*)(qkv + base + (size_t)(qb * 128 + row) * D3 + hoff + c2 * 2);
    }
    loadKV(0, 0); cp_commit();
    __syncthreads();

    // Q fragments, pre-scaled by 1/8 (exact in half)
    uint32_t qf[4][4];
    const __half2 hsc = __floats2half2_rn(0.125f, 0.125f);
    #pragma unroll
    for (int kc = 0; kc < 4; kc++) {
        int row = w * 16 + (lane & 7) + ((lane >> 3) & 1) * 8;
        int col = kc * 16 + (lane >> 4) * 8;
        ldsm4(qf[kc][0], qf[kc][1], qf[kc][2], qf[kc][3],
              smem_u32(&Qs[row * ATS + col]));
        #pragma unroll
        for (int i = 0; i < 4; i++) {
            __half2 v = __hmul2(*(__half2*)&qf[kc][i], hsc);
            qf[kc][i] = *(uint32_t*)&v;
        }
    }

    float o[8][4];
    #pragma unroll
    for (int n = 0; n < 8; n++)
        #pragma unroll
        for (int i = 0; i < 4; i++) o[n][i] = 0.f;
    float m0r = -INFINITY, m1r = -INFINITY, l0r = 0.f, l1r = 0.f;

    int rowq0 = qb * 128 + w * 16 + g;
    int rowq1 = rowq0 + 8;
    int kbmax = 2 * qb + 1;

    for (int kb = 0; kb <= kbmax; kb++) {
        int st = kb & 1;
        if (kb < kbmax) { loadKV(kb + 1, st ^ 1); cp_commit(); cp_wait<1>(); }
        else            { cp_wait<0>(); }
        __syncthreads();

        uint32_t stK = sbKV + (uint32_t)((st * 2) * 64 * ATS) * 2;
        uint32_t stV = sbKV + (uint32_t)((st * 2 + 1) * 64 * ATS) * 2;

        // ---- S = (Q/8) K^T ----
        float c[8][4];
        #pragma unroll
        for (int n = 0; n < 8; n++)
            #pragma unroll
            for (int i = 0; i < 4; i++) c[n][i] = 0.f;

        #pragma unroll
        for (int kc = 0; kc < 4; kc++) {
            #pragma unroll
            for (int n16 = 0; n16 < 4; n16++) {
                uint32_t r0, r1, r2, r3;
                int row = n16 * 16 + (lane & 7) + ((lane >> 3) & 1) * 8;
                int col = kc * 16 + (lane >> 4) * 8;
                ldsm4(r0, r1, r2, r3, stK + (uint32_t)(row * ATS + col) * 2);
                uint32_t b0[2] = {r0, r2}, b1[2] = {r1, r3};
                mma16816(c[2 * n16],     qf[kc], b0);
                mma16816(c[2 * n16 + 1], qf[kc], b1);
            }
        }

        // ---- online softmax ----
        float smax0 = -1e30f, smax1 = -1e30f;
        bool diag = (kb >= 2 * qb);
        #pragma unroll
        for (int n = 0; n < 8; n++) {
            int col = kb * 64 + n * 8 + 2 * t;
            if (diag) {
                if (col     > rowq0) c[n][0] = -1e30f;
                if (col + 1 > rowq0) c[n][1] = -1e30f;
                if (col     > rowq1) c[n][2] = -1e30f;
                if (col + 1 > rowq1) c[n][3] = -1e30f;
            }
            smax0 = fmaxf(smax0, fmaxf(c[n][0], c[n][1]));
            smax1 = fmaxf(smax1, fmaxf(c[n][2], c[n][3]));
        }
        smax0 = fmaxf(smax0, __shfl_xor_sync(0xffffffffu, smax0, 1));
        smax0 = fmaxf(smax0, __shfl_xor_sync(0xffffffffu, smax0, 2));
        smax1 = fmaxf(smax1, __shfl_xor_sync(0xffffffffu, smax1, 1));
        smax1 = fmaxf(smax1, __shfl_xor_sync(0xffffffffu, smax1, 2));

        float mn0 = fmaxf(m0r, smax0), mn1 = fmaxf(m1r, smax1);
        float f0 = __expf(m0r - mn0),  f1 = __expf(m1r - mn1);
        m0r = mn0; m1r = mn1;

        float s0 = 0.f, s1 = 0.f;
        #pragma unroll
        for (int n = 0; n < 8; n++) {
            c[n][0] = __expf(c[n][0] - mn0); c[n][1] = __expf(c[n][1] - mn0);
            c[n][2] = __expf(c[n][2] - mn1); c[n][3] = __expf(c[n][3] - mn1);
            s0 += c[n][0] + c[n][1];
            s1 += c[n][2] + c[n][3];
        }
        s0 += __shfl_xor_sync(0xffffffffu, s0, 1);
        s0 += __shfl_xor_sync(0xffffffffu, s0, 2);
        s1 += __shfl_xor_sync(0xffffffffu, s1, 1);
        s1 += __shfl_xor_sync(0xffffffffu, s1, 2);
        l0r = l0r * f0 + s0;
        l1r = l1r * f1 + s1;

        #pragma unroll
        for (int n = 0; n < 8; n++) {
            o[n][0] *= f0; o[n][1] *= f0;
            o[n][2] *= f1; o[n][3] *= f1;
        }

        // ---- O += P V : V B-frags via ldmatrix.trans ----
        #pragma unroll
        for (int kc = 0; kc < 4; kc++) {
            uint32_t pa[4];
            pa[0] = pack_h2(c[2 * kc][0],     c[2 * kc][1]);
            pa[1] = pack_h2(c[2 * kc][2],     c[2 * kc][3]);
            pa[2] = pack_h2(c[2 * kc + 1][0], c[2 * kc + 1][1]);
            pa[3] = pack_h2(c[2 * kc + 1][2], c[2 * kc + 1][3]);
            #pragma unroll
            for (int d16 = 0; d16 < 4; d16++) {
                uint32_t r0, r1, r2, r3;
                int m = lane >> 3;
                int row = kc * 16 + (m & 1) * 8 + (lane & 7);
                int col = d16 * 16 + (m >> 1) * 8;
                ldsm4t(r0, r1, r2, r3, stV + (uint32_t)(row * ATS + col) * 2);
                uint32_t b0[2] = {r0, r1}, b1[2] = {r2, r3};
                mma16816(o[2 * d16],     pa, b0);
                mma16816(o[2 * d16 + 1], pa, b1);
            }
        }
        __syncthreads();
    }

    // ---- epilogue ----
    float inv0 = 1.0f / l0r, inv1 = 1.0f / l1r;
    size_t r0 = (size_t)(b * TSEQ + qb * 128 + w * 16 + g) * DMODEL + hoff;
    size_t r1 = r0 + (size_t)8 * DMODEL;
    #pragma unroll
    for (int n = 0; n < 8; n++) {
        int col = n * 8 + 2 * t;
        *(__half2*)(y + r0 + col) = __floats2half2_rn(o[n][0] * inv0, o[n][1] * inv0);
        *(__half2*)(y + r1 + col) = __floats2half2_rn(o[n][2] * inv1, o[n][3] * inv1);
    }
}

// ---------------- launch ----------------------------------------------------
template <typename T>
static T* symaddr(const void* sym) {
    void* p = nullptr;
    cudaGetSymbolAddress(&p, sym);
    return (T*)p;
}

extern "C" void kernel_launch(void* const* d_in, const int* in_sizes, int n_in,
                              void* d_out, int out_size) {
    const float* x      = (const float*)d_in[0];
    const float* ln1_w  = (const float*)d_in[1];
    const float* ln1_b  = (const float*)d_in[2];
    const float* qkv_w  = (const float*)d_in[3];
    const float* qkv_b  = (const float*)d_in[4];
    const float* out_w  = (const float*)d_in[5];
    const float* out_b  = (const float*)d_in[6];
    const float* ln2_w  = (const float*)d_in[7];
    const float* ln2_b  = (const float*)d_in[8];
    const float* mlp_w1 = (const float*)d_in[9];
    const float* mlp_b1 = (const float*)d_in[10];
    const float* mlp_w2 = (const float*)d_in[11];
    const float* mlp_b2 = (const float*)d_in[12];
    float* out = (float*)d_out;

    float*  x1   = symaddr<float>(g_x1);
    __half* qkvh = symaddr<__half>(g_qkv_h);
    __half* xlnh = symaddr<__half>(g_xln_h);
    __half* yh   = symaddr<__half>(g_y_h);
    __half* hh   = symaddr<__half>(g_h_h);
    __half* acth = symaddr<__half>(g_act_h);
    __half* wqh  = symaddr<__half>(g_wq_h);
    __half* woh  = symaddr<__half>(g_wo_h);
    __half* w1h  = symaddr<__half>(g_w1_h);
    __half* w2h  = symaddr<__half>(g_w2_h);

    cudaFuncSetAttribute(gemm_h<0,1>, cudaFuncAttributeMaxDynamicSharedMemorySize, GEMM_SMEM);
    cudaFuncSetAttribute(gemm_h<1,1>, cudaFuncAttributeMaxDynamicSharedMemorySize, GEMM_SMEM);
    cudaFuncSetAttribute(gemm_h<2,0>, cudaFuncAttributeMaxDynamicSharedMemorySize, GEMM_SMEM);
    cudaFuncSetAttribute(attn_h, cudaFuncAttributeMaxDynamicSharedMemorySize, ATT_SMEM);

    // 0. weights -> half (single fused launch; grid.y selects the matrix)
    {
        int n_wq = D3 * DMODEL / 4, n_wo = DMODEL * DMODEL / 4;
        int n_w1 = DFF * DMODEL / 4, n_w2 = DMODEL * DFF / 4;
        int maxb = (n_w1 / 2 + 255) / 256;   // w1/w2 are largest
        f2h4_kernel<<<dim3(maxb, 4), 256>>>(
            (const float4*)qkv_w, (__half2*)wqh, n_wq,
            (const float4*)out_w, (__half2*)woh, n_wo,
            (const float4*)mlp_w1, (__half2*)w1h, n_w1,
            (const float4*)mlp_w2, (__half2*)w2h, n_w2);
    }

    // 1. LN1 -> half
    ln_kernel<<<MROWS, 256>>>(x, ln1_w, ln1_b, xlnh);
    // 2. QKV projection -> half qkv
    gemm_h<0,1><<<dim3(D3 / 128, MROWS / 128), 256, GEMM_SMEM>>>(xlnh, wqh, qkv_b, nullptr, nullptr, qkvh, D3, DMODEL);
    // 3. causal attention (fp16 mma, Q-tile 128) -> half y
    attn_h<<<dim3(TSEQ / 128, NHEAD, 2), 256, ATT_SMEM>>>(qkvh, yh);
    // 4. out projection + residual -> fp32 x1
    gemm_h<2,0><<<dim3(DMODEL / 128, MROWS / 128), 256, GEMM_SMEM>>>(yh, woh, out_b, x, x1, nullptr, DMODEL, DMODEL);
    // 5. LN2 -> half
    ln_kernel<<<MROWS, 256>>>(x1, ln2_w, ln2_b, hh);
    // 6. MLP up + exact GELU -> half act
    gemm_h<1,1><<<dim3(DFF / 128, MROWS / 128), 256, GEMM_SMEM>>>(hh, w1h, mlp_b1, nullptr, nullptr, acth, DFF, DMODEL);
    // 7. MLP down + residual -> fp32 output
    gemm_h<2,0><<<dim3(DMODEL / 128, MROWS / 128), 256, GEMM_SMEM>>>(acth, w2h, mlp_b2, x1, out, nullptr, DMODEL, DFF);
}

// round 13
// speedup vs baseline: 1.0308x; 1.0308x over previous
#include <cuda_runtime.h>
#include <cuda_fp16.h>
#include <math.h>
#include <stdint.h>

// Problem constants
#define MROWS  4096      // B*T
#define DMODEL 1024
#define D3     3072
#define DFF    4096
#define TSEQ   2048
#define NHEAD  16
#define DHEAD  64

// ---------------- scratch (device globals: no runtime allocation) ----------
__device__ float g_x1 [(size_t)MROWS * DMODEL];
__device__ __align__(16) __half g_qkv_h[(size_t)MROWS * D3];
__device__ __align__(16) __half g_xln_h[(size_t)MROWS * DMODEL];
__device__ __align__(16) __half g_y_h  [(size_t)MROWS * DMODEL];
__device__ __align__(16) __half g_h_h  [(size_t)MROWS * DMODEL];
__device__ __align__(16) __half g_act_h[(size_t)MROWS * DFF];
__device__ __align__(16) __half g_wq_h [(size_t)D3 * DMODEL];
__device__ __align__(16) __half g_wo_h [(size_t)DMODEL * DMODEL];
__device__ __align__(16) __half g_w1_h [(size_t)DFF * DMODEL];
__device__ __align__(16) __half g_w2_h [(size_t)DMODEL * DFF];

// ---------------- helpers ---------------------------------------------------
__device__ __forceinline__ uint32_t smem_u32(const void* p) {
    uint32_t a;
    asm("{ .reg .u64 t; cvta.to.shared.u64 t, %1; cvt.u32.u64 %0, t; }" : "=r"(a) : "l"(p));
    return a;
}
__device__ __forceinline__ void cpa16(uint32_t s, const void* g) {
    asm volatile("cp.async.cg.shared.global [%0], [%1], 16;" :: "r"(s), "l"(g));
}
__device__ __forceinline__ void cp_commit() { asm volatile("cp.async.commit_group;"); }
template <int N>
__device__ __forceinline__ void cp_wait() { asm volatile("cp.async.wait_group %0;" :: "n"(N)); }

__device__ __forceinline__ void ldsm4(uint32_t& r0, uint32_t& r1, uint32_t& r2, uint32_t& r3,
                                      uint32_t addr) {
    asm volatile("ldmatrix.sync.aligned.m8n8.x4.shared.b16 {%0,%1,%2,%3}, [%4];"
                 : "=r"(r0), "=r"(r1), "=r"(r2), "=r"(r3) : "r"(addr));
}
__device__ __forceinline__ void ldsm4t(uint32_t& r0, uint32_t& r1, uint32_t& r2, uint32_t& r3,
                                       uint32_t addr) {
    asm volatile("ldmatrix.sync.aligned.m8n8.x4.trans.shared.b16 {%0,%1,%2,%3}, [%4];"
                 : "=r"(r0), "=r"(r1), "=r"(r2), "=r"(r3) : "r"(addr));
}

__device__ __forceinline__ float gelu_exact(float v) {
    return 0.5f * v * (1.0f + erff(v * 0.70710678118654752f));
}

// mma.m16n8k16 fp16 -> fp32, row.col
__device__ __forceinline__ void mma16816(float* c, const uint32_t* a, const uint32_t* b) {
    asm volatile(
        "mma.sync.aligned.m16n8k16.row.col.f32.f16.f16.f32 "
        "{%0,%1,%2,%3}, {%4,%5,%6,%7}, {%8,%9}, {%0,%1,%2,%3};"
        : "+f"(c[0]), "+f"(c[1]), "+f"(c[2]), "+f"(c[3])
        : "r"(a[0]), "r"(a[1]), "r"(a[2]), "r"(a[3]), "r"(b[0]), "r"(b[1]));
}
__device__ __forceinline__ uint32_t pack_h2(float x, float y) {
    __half2 h = __floats2half2_rn(x, y);
    return *(uint32_t*)&h;
}

// ---------------- fused float -> half convert (4 arrays, grid.y selects) ----
__global__ void f2h4_kernel(const float4* s0, __half2* d0, int n0,
                            const float4* s1, __half2* d1, int n1,
                            const float4* s2, __half2* d2, int n2,
                            const float4* s3, __half2* d3, int n3) {
    const float4* src; __half2* dst; int n4;
    switch (blockIdx.y) {
        case 0: src = s0; dst = d0; n4 = n0; break;
        case 1: src = s1; dst = d1; n4 = n1; break;
        case 2: src = s2; dst = d2; n4 = n2; break;
        default: src = s3; dst = d3; n4 = n3; break;
    }
    int half_n = n4 >> 1;
    int i = blockIdx.x * blockDim.x + threadIdx.x;
    if (i < half_n) {
        float4 v0 = src[i];
        float4 v1 = src[i + half_n];
        dst[2 * i]     = __floats2half2_rn(v0.x, v0.y);
        dst[2 * i + 1] = __floats2half2_rn(v0.z, v0.w);
        dst[2 * (i + half_n)]     = __floats2half2_rn(v1.x, v1.y);
        dst[2 * (i + half_n) + 1] = __floats2half2_rn(v1.z, v1.w);
    }
}

// ---------------- LayerNorm (fp32 in, half out) -----------------------------
__global__ void ln_kernel(const float* __restrict__ x,
                          const float* __restrict__ w,
                          const float* __restrict__ b,
                          __half* __restrict__ out) {
    int row = blockIdx.x;
    int tid = threadIdx.x;
    const float* xr = x + (size_t)row * DMODEL;

    float4 v = *(const float4*)(xr + tid * 4);
    float s  = v.x + v.y + v.z + v.w;
    float ss = v.x * v.x + v.y * v.y + v.z * v.z + v.w * v.w;

    #pragma unroll
    for (int off = 16; off >= 1; off >>= 1) {
        s  += __shfl_xor_sync(0xffffffffu, s,  off);
        ss += __shfl_xor_sync(0xffffffffu, ss, off);
    }
    __shared__ float rs[8], rss[8];
    __shared__ float stats[2];
    int wid = tid >> 5, lane = tid & 31;
    if (lane == 0) { rs[wid] = s; rss[wid] = ss; }
    __syncthreads();
    if (tid == 0) {
        float S = 0.f, SS = 0.f;
        #pragma unroll
        for (int i = 0; i < 8; i++) { S += rs[i]; SS += rss[i]; }
        float mu  = S * (1.0f / DMODEL);
        float var = SS * (1.0f / DMODEL) - mu * mu;
        stats[0] = mu;
        stats[1] = rsqrtf(var + 1e-5f);
    }
    __syncthreads();
    float mu = stats[0], r = stats[1];

    float4 wv = *(const float4*)(w + tid * 4);
    float4 bv = *(const float4*)(b + tid * 4);
    float o0 = (v.x - mu) * r * wv.x + bv.x;
    float o1 = (v.y - mu) * r * wv.y + bv.y;
    float o2 = (v.z - mu) * r * wv.z + bv.z;
    float o3 = (v.w - mu) * r * wv.w + bv.w;
    __half2* orow = (__half2*)(out + (size_t)row * DMODEL);
    orow[tid * 2]     = __floats2half2_rn(o0, o1);
    orow[tid * 2 + 1] = __floats2half2_rn(o2, o3);
}

// ---------------- fp16 GEMM NT: ldmatrix + mma, swizzled smem ----------------
// (frozen — at the legacy-HMMA ceiling)
#define GK 64
#define NSTG 3
#define TILE_H (128 * 64)
#define STG_B (2 * TILE_H * 2)
#define GEMM_SMEM (NSTG * STG_B)          // 98304 bytes

__device__ __forceinline__ uint32_t swz(int row, int ch) {
    return (uint32_t)(row * 64 + ((ch ^ (row & 7)) * 8));
}

template <int EPI, int HOUT>
__global__ void __launch_bounds__(256, 2)
gemm_h(const __half* __restrict__ A, const __half* __restrict__ B,
       const float* __restrict__ bias, const float* __restrict__ res,
       float* __restrict__ C, __half* __restrict__ Ch, int N, int K) {
    extern __shared__ __align__(16) __half sm[];
    uint32_t sb = smem_u32(sm);

    int tid = threadIdx.x;
    int wid = tid >> 5, lane = tid & 31;
    int g = lane >> 2, t = lane & 3;
    int bn = blockIdx.x, bm = blockIdx.y;
    int wm = wid & 3;
    int wn = wid >> 2;
    const int KT = K / GK;

    float acc[2][8][4];
    #pragma unroll
    for (int mt = 0; mt < 2; mt++)
        #pragma unroll
        for (int n = 0; n < 8; n++)
            #pragma unroll
            for (int i = 0; i < 4; i++) acc[mt][n][i] = 0.f;

    const __half* Ab = A + (size_t)(bm * 128) * K;
    const __half* Bb = B + (size_t)(bn * 128) * K;

    auto issue = [&](int kt) {
        uint32_t dst = sb + (uint32_t)(kt % NSTG) * STG_B;
        #pragma unroll
        for (int i = 0; i < 4; i++) {
            int c = i * 256 + tid;
            int row = c >> 3, ch = c & 7;
            cpa16(dst + swz(row, ch) * 2,              Ab + (size_t)row * K + kt * GK + ch * 8);
            cpa16(dst + TILE_H * 2 + swz(row, ch) * 2, Bb + (size_t)row * K + kt * GK + ch * 8);
        }
    };

    issue(0); cp_commit();
    issue(1); cp_commit();

    for (int kt = 0; kt < KT; kt++) {
        bool more = (kt + 2 < KT);
        if (more) cp_wait<1>();
        else      cp_wait<0>();
        __syncthreads();
        if (more) { issue(kt + 2); cp_commit(); }

        uint32_t stA = sb + (uint32_t)(kt % NSTG) * STG_B;
        uint32_t stB = stA + TILE_H * 2;

        #pragma unroll
        for (int kk = 0; kk < 4; kk++) {
            uint32_t a[2][4];
            #pragma unroll
            for (int mt = 0; mt < 2; mt++) {
                int row = wm * 32 + mt * 16 + (lane & 7) + ((lane >> 3) & 1) * 8;
                int ch  = kk * 2 + (lane >> 4);
                ldsm4(a[mt][0], a[mt][1], a[mt][2], a[mt][3], stA + swz(row, ch) * 2);
            }
            uint32_t bfr[8][2];
            #pragma unroll
            for (int np = 0; np < 4; np++) {
                uint32_t r0, r1, r2, r3;
                int row = wn * 64 + np * 16 + (lane & 7) + ((lane >> 3) & 1) * 8;
                int ch  = kk * 2 + (lane >> 4);
                ldsm4(r0, r1, r2, r3, stB + swz(row, ch) * 2);
                bfr[np * 2][0]     = r0; bfr[np * 2][1]     = r2;
                bfr[np * 2 + 1][0] = r1; bfr[np * 2 + 1][1] = r3;
            }
            #pragma unroll
            for (int mt = 0; mt < 2; mt++)
                #pragma unroll
                for (int n = 0; n < 8; n++)
                    mma16816(acc[mt][n], a[mt], bfr[n]);
        }
    }

    __syncthreads();
    float* Cs = (float*)sm;
    #pragma unroll
    for (int mt = 0; mt < 2; mt++)
        #pragma unroll
        for (int n = 0; n < 8; n++) {
            int r0 = wm * 32 + mt * 16 + g;
            int c0 = wn * 64 + n * 8 + 2 * t;
            Cs[r0 * 132 + c0]           = acc[mt][n][0];
            Cs[r0 * 132 + c0 + 1]       = acc[mt][n][1];
            Cs[(r0 + 8) * 132 + c0]     = acc[mt][n][2];
            Cs[(r0 + 8) * 132 + c0 + 1] = acc[mt][n][3];
        }
    __syncthreads();

    int m0 = bm * 128, n0 = bn * 128;
    #pragma unroll
    for (int it = 0; it < 16; it++) {
        int idx = tid + it * 256;
        int r  = idx >> 5;
        int c4 = (idx & 31) * 4;
        float4 v = *(const float4*)&Cs[r * 132 + c4];
        float4 bv = *(const float4*)(bias + n0 + c4);
        v.x += bv.x; v.y += bv.y; v.z += bv.z; v.w += bv.w;
        if (EPI == 1) {
            v.x = gelu_exact(v.x); v.y = gelu_exact(v.y);
            v.z = gelu_exact(v.z); v.w = gelu_exact(v.w);
        }
        size_t off = (size_t)(m0 + r) * N + n0 + c4;
        if (EPI == 2) {
            float4 rv = *(const float4*)(res + off);
            v.x += rv.x; v.y += rv.y; v.z += rv.z; v.w += rv.w;
        }
        if (HOUT) {
            __half2* hp = (__half2*)(Ch + off);
            hp[0] = __floats2half2_rn(v.x, v.y);
            hp[1] = __floats2half2_rn(v.z, v.w);
        } else {
            *(float4*)(C + off) = v;
        }
    }
}

// ---------------- FA2 fp16 attention (round-9 config + base-2 softmax) ------
// grid (T/64, H, B), 4 warps, static smem, K/V double-buffered cp.async.
// Q pre-scaled by log2(e)/8 so S is in log2 domain; exp2f everywhere.
#define ATS 72    // smem stride in halves

__global__ void __launch_bounds__(128)
attn_h(const __half* __restrict__ qkv, __half* __restrict__ y) {
    __shared__ __align__(16) __half Qs[64 * ATS];
    __shared__ __align__(16) __half KV[2][2][64 * ATS];   // [stage][K/V][row][col]

    int qb = blockIdx.x, h = blockIdx.y, b = blockIdx.z;
    int tid = threadIdx.x;
    int w = tid >> 5, lane = tid & 31;
    int g = lane >> 2, t = lane & 3;
    size_t base = (size_t)b * TSEQ * D3;
    int hoff = h * DHEAD;

    uint32_t sbKV = smem_u32(&KV[0][0][0]);

    auto loadKV = [&](int kb, int st) {
        #pragma unroll
        for (int i = 0; i < 8; i++) {
            int idx = tid + i * 128;            // 0..1023
            int isV = idx >> 9;
            int row = (idx >> 3) & 63;
            int ch  = idx & 7;
            const __half* src = qkv + base + (size_t)(kb * 64 + row) * D3 + hoff
                               + 1024 + isV * 1024 + ch * 8;
            cpa16(sbKV + (uint32_t)(((st * 2 + isV) * 64 + row) * ATS + ch * 8) * 2, src);
        }
    };

    // load Q tile + prefetch KV(0)
    #pragma unroll
    for (int i = 0; i < 16; i++) {
        int idx = tid + i * 128;
        int row = idx >> 5, c2 = idx & 31;
        *(__half2*)&Qs[row * ATS + c2 * 2] =
            *(const __half2*)(qkv + base + (size_t)(qb * 64 + row) * D3 + hoff + c2 * 2);
    }
    loadKV(0, 0); cp_commit();
    __syncthreads();

    // Q fragments, pre-scaled by log2(e)/8 (base-2 softmax domain)
    uint32_t qf[4][4];
    const __half2 hsc = __floats2half2_rn(0.18033688f, 0.18033688f);
    #pragma unroll
    for (int kc = 0; kc < 4; kc++) {
        int row = w * 16 + (lane & 7) + ((lane >> 3) & 1) * 8;
        int col = kc * 16 + (lane >> 4) * 8;
        ldsm4(qf[kc][0], qf[kc][1], qf[kc][2], qf[kc][3],
              smem_u32(&Qs[row * ATS + col]));
        #pragma unroll
        for (int i = 0; i < 4; i++) {
            __half2 v = __hmul2(*(__half2*)&qf[kc][i], hsc);
            qf[kc][i] = *(uint32_t*)&v;
        }
    }

    float o[8][4];
    #pragma unroll
    for (int n = 0; n < 8; n++)
        #pragma unroll
        for (int i = 0; i < 4; i++) o[n][i] = 0.f;
    float m0r = -INFINITY, m1r = -INFINITY, l0r = 0.f, l1r = 0.f;

    int rowq0 = qb * 64 + w * 16 + g;
    int rowq1 = rowq0 + 8;

    for (int kb = 0; kb <= qb; kb++) {
        int st = kb & 1;
        if (kb < qb) { loadKV(kb + 1, st ^ 1); cp_commit(); cp_wait<1>(); }
        else         { cp_wait<0>(); }
        __syncthreads();

        uint32_t stK = sbKV + (uint32_t)((st * 2) * 64 * ATS) * 2;
        uint32_t stV = sbKV + (uint32_t)((st * 2 + 1) * 64 * ATS) * 2;

        // ---- S2 = (Q*log2e/8) K^T  (log2 domain) ----
        float c[8][4];
        #pragma unroll
        for (int n = 0; n < 8; n++)
            #pragma unroll
            for (int i = 0; i < 4; i++) c[n][i] = 0.f;

        #pragma unroll
        for (int kc = 0; kc < 4; kc++) {
            #pragma unroll
            for (int n16 = 0; n16 < 4; n16++) {
                uint32_t r0, r1, r2, r3;
                int row = n16 * 16 + (lane & 7) + ((lane >> 3) & 1) * 8;
                int col = kc * 16 + (lane >> 4) * 8;
                ldsm4(r0, r1, r2, r3, stK + (uint32_t)(row * ATS + col) * 2);
                uint32_t b0[2] = {r0, r2}, b1[2] = {r1, r3};
                mma16816(c[2 * n16],     qf[kc], b0);
                mma16816(c[2 * n16 + 1], qf[kc], b1);
            }
        }

        // ---- online softmax, base 2 ----
        float smax0 = -1e30f, smax1 = -1e30f;
        #pragma unroll
        for (int n = 0; n < 8; n++) {
            int col = kb * 64 + n * 8 + 2 * t;
            if (kb == qb) {
                if (col     > rowq0) c[n][0] = -1e30f;
                if (col + 1 > rowq0) c[n][1] = -1e30f;
                if (col     > rowq1) c[n][2] = -1e30f;
                if (col + 1 > rowq1) c[n][3] = -1e30f;
            }
            smax0 = fmaxf(smax0, fmaxf(c[n][0], c[n][1]));
            smax1 = fmaxf(smax1, fmaxf(c[n][2], c[n][3]));
        }
        smax0 = fmaxf(smax0, __shfl_xor_sync(0xffffffffu, smax0, 1));
        smax0 = fmaxf(smax0, __shfl_xor_sync(0xffffffffu, smax0, 2));
        smax1 = fmaxf(smax1, __shfl_xor_sync(0xffffffffu, smax1, 1));
        smax1 = fmaxf(smax1, __shfl_xor_sync(0xffffffffu, smax1, 2));

        float mn0 = fmaxf(m0r, smax0), mn1 = fmaxf(m1r, smax1);
        float f0 = exp2f(m0r - mn0),  f1 = exp2f(m1r - mn1);
        m0r = mn0; m1r = mn1;

        float s0 = 0.f, s1 = 0.f;
        #pragma unroll
        for (int n = 0; n < 8; n++) {
            c[n][0] = exp2f(c[n][0] - mn0); c[n][1] = exp2f(c[n][1] - mn0);
            c[n][2] = exp2f(c[n][2] - mn1); c[n][3] = exp2f(c[n][3] - mn1);
            s0 += c[n][0] + c[n][1];
            s1 += c[n][2] + c[n][3];
        }
        s0 += __shfl_xor_sync(0xffffffffu, s0, 1);
        s0 += __shfl_xor_sync(0xffffffffu, s0, 2);
        s1 += __shfl_xor_sync(0xffffffffu, s1, 1);
        s1 += __shfl_xor_sync(0xffffffffu, s1, 2);
        l0r = l0r * f0 + s0;
        l1r = l1r * f1 + s1;

        #pragma unroll
        for (int n = 0; n < 8; n++) {
            o[n][0] *= f0; o[n][1] *= f0;
            o[n][2] *= f1; o[n][3] *= f1;
        }

        // ---- O += P V : V B-frags via ldmatrix.trans ----
        #pragma unroll
        for (int kc = 0; kc < 4; kc++) {
            uint32_t pa[4];
            pa[0] = pack_h2(c[2 * kc][0],     c[2 * kc][1]);
            pa[1] = pack_h2(c[2 * kc][2],     c[2 * kc][3]);
            pa[2] = pack_h2(c[2 * kc + 1][0], c[2 * kc + 1][1]);
            pa[3] = pack_h2(c[2 * kc + 1][2], c[2 * kc + 1][3]);
            #pragma unroll
            for (int d16 = 0; d16 < 4; d16++) {
                uint32_t r0, r1, r2, r3;
                int m = lane >> 3;
                int row = kc * 16 + (m & 1) * 8 + (lane & 7);
                int col = d16 * 16 + (m >> 1) * 8;
                ldsm4t(r0, r1, r2, r3, stV + (uint32_t)(row * ATS + col) * 2);
                uint32_t b0[2] = {r0, r1}, b1[2] = {r2, r3};
                mma16816(o[2 * d16],     pa, b0);
                mma16816(o[2 * d16 + 1], pa, b1);
            }
        }
        __syncthreads();
    }

    // ---- epilogue ----
    float inv0 = 1.0f / l0r, inv1 = 1.0f / l1r;
    size_t r0 = (size_t)(b * TSEQ + qb * 64 + w * 16 + g) * DMODEL + hoff;
    size_t r1 = r0 + (size_t)8 * DMODEL;
    #pragma unroll
    for (int n = 0; n < 8; n++) {
        int col = n * 8 + 2 * t;
        *(__half2*)(y + r0 + col) = __floats2half2_rn(o[n][0] * inv0, o[n][1] * inv0);
        *(__half2*)(y + r1 + col) = __floats2half2_rn(o[n][2] * inv1, o[n][3] * inv1);
    }
}

// ---------------- launch ----------------------------------------------------
template <typename T>
static T* symaddr(const void* sym) {
    void* p = nullptr;
    cudaGetSymbolAddress(&p, sym);
    return (T*)p;
}

extern "C" void kernel_launch(void* const* d_in, const int* in_sizes, int n_in,
                              void* d_out, int out_size) {
    const float* x      = (const float*)d_in[0];
    const float* ln1_w  = (const float*)d_in[1];
    const float* ln1_b  = (const float*)d_in[2];
    const float* qkv_w  = (const float*)d_in[3];
    const float* qkv_b  = (const float*)d_in[4];
    const float* out_w  = (const float*)d_in[5];
    const float* out_b  = (const float*)d_in[6];
    const float* ln2_w  = (const float*)d_in[7];
    const float* ln2_b  = (const float*)d_in[8];
    const float* mlp_w1 = (const float*)d_in[9];
    const float* mlp_b1 = (const float*)d_in[10];
    const float* mlp_w2 = (const float*)d_in[11];
    const float* mlp_b2 = (const float*)d_in[12];
    float* out = (float*)d_out;

    float*  x1   = symaddr<float>(g_x1);
    __half* qkvh = symaddr<__half>(g_qkv_h);
    __half* xlnh = symaddr<__half>(g_xln_h);
    __half* yh   = symaddr<__half>(g_y_h);
    __half* hh   = symaddr<__half>(g_h_h);
    __half* acth = symaddr<__half>(g_act_h);
    __half* wqh  = symaddr<__half>(g_wq_h);
    __half* woh  = symaddr<__half>(g_wo_h);
    __half* w1h  = symaddr<__half>(g_w1_h);
    __half* w2h  = symaddr<__half>(g_w2_h);

    cudaFuncSetAttribute(gemm_h<0,1>, cudaFuncAttributeMaxDynamicSharedMemorySize, GEMM_SMEM);
    cudaFuncSetAttribute(gemm_h<1,1>, cudaFuncAttributeMaxDynamicSharedMemorySize, GEMM_SMEM);
    cudaFuncSetAttribute(gemm_h<2,0>, cudaFuncAttributeMaxDynamicSharedMemorySize, GEMM_SMEM);

    // 0. weights -> half (single fused launch)
    {
        int n_wq = D3 * DMODEL / 4, n_wo = DMODEL * DMODEL / 4;
        int n_w1 = DFF * DMODEL / 4, n_w2 = DMODEL * DFF / 4;
        int maxb = (n_w1 / 2 + 255) / 256;
        f2h4_kernel<<<dim3(maxb, 4), 256>>>(
            (const float4*)qkv_w, (__half2*)wqh, n_wq,
            (const float4*)out_w, (__half2*)woh, n_wo,
            (const float4*)mlp_w1, (__half2*)w1h, n_w1,
            (const float4*)mlp_w2, (__half2*)w2h, n_w2);
    }

    // 1. LN1 -> half
    ln_kernel<<<MROWS, 256>>>(x, ln1_w, ln1_b, xlnh);
    // 2. QKV projection -> half qkv
    gemm_h<0,1><<<dim3(D3 / 128, MROWS / 128), 256, GEMM_SMEM>>>(xlnh, wqh, qkv_b, nullptr, nullptr, qkvh, D3, DMODEL);
    // 3. causal attention (fp16 mma, 64-q tile, base-2 softmax) -> half y
    attn_h<<<dim3(TSEQ / 64, NHEAD, 2), 128>>>(qkvh, yh);
    // 4. out projection + residual -> fp32 x1
    gemm_h<2,0><<<dim3(DMODEL / 128, MROWS / 128), 256, GEMM_SMEM>>>(yh, woh, out_b, x, x1, nullptr, DMODEL, DMODEL);
    // 5. LN2 -> half
    ln_kernel<<<MROWS, 256>>>(x1, ln2_w, ln2_b, hh);
    // 6. MLP up + exact GELU -> half act
    gemm_h<1,1><<<dim3(DFF / 128, MROWS / 128), 256, GEMM_SMEM>>>(hh, w1h, mlp_b1, nullptr, nullptr, acth, DFF, DMODEL);
    // 7. MLP down + residual -> fp32 output
    gemm_h<2,0><<<dim3(DMODEL / 128, MROWS / 128), 256, GEMM_SMEM>>>(acth, w2h, mlp_b2, x1, out, nullptr, DMODEL, DFF);
}

// round 14
// speedup vs baseline: 1.0349x; 1.0040x over previous
#include <cuda_runtime.h>
#include <cuda_fp16.h>
#include <math.h>
#include <stdint.h>

// Problem constants
#define MROWS  4096      // B*T
#define DMODEL 1024
#define D3     3072
#define DFF    4096
#define TSEQ   2048
#define NHEAD  16
#define DHEAD  64

// ---------------- scratch (device globals: no runtime allocation) ----------
__device__ float g_x1 [(size_t)MROWS * DMODEL];
__device__ __align__(16) __half g_qkv_h[(size_t)MROWS * D3];
__device__ __align__(16) __half g_xln_h[(size_t)MROWS * DMODEL];
__device__ __align__(16) __half g_y_h  [(size_t)MROWS * DMODEL];
__device__ __align__(16) __half g_h_h  [(size_t)MROWS * DMODEL];
__device__ __align__(16) __half g_act_h[(size_t)MROWS * DFF];
__device__ __align__(16) __half g_wq_h [(size_t)D3 * DMODEL];
__device__ __align__(16) __half g_wo_h [(size_t)DMODEL * DMODEL];
__device__ __align__(16) __half g_w1_h [(size_t)DFF * DMODEL];
__device__ __align__(16) __half g_w2_h [(size_t)DMODEL * DFF];

// ---------------- helpers ---------------------------------------------------
__device__ __forceinline__ uint32_t smem_u32(const void* p) {
    uint32_t a;
    asm("{ .reg .u64 t; cvta.to.shared.u64 t, %1; cvt.u32.u64 %0, t; }" : "=r"(a) : "l"(p));
    return a;
}
__device__ __forceinline__ void cpa16(uint32_t s, const void* g) {
    asm volatile("cp.async.cg.shared.global [%0], [%1], 16;" :: "r"(s), "l"(g));
}
__device__ __forceinline__ void cp_commit() { asm volatile("cp.async.commit_group;"); }
template <int N>
__device__ __forceinline__ void cp_wait() { asm volatile("cp.async.wait_group %0;" :: "n"(N)); }

__device__ __forceinline__ void ldsm4(uint32_t& r0, uint32_t& r1, uint32_t& r2, uint32_t& r3,
                                      uint32_t addr) {
    asm volatile("ldmatrix.sync.aligned.m8n8.x4.shared.b16 {%0,%1,%2,%3}, [%4];"
                 : "=r"(r0), "=r"(r1), "=r"(r2), "=r"(r3) : "r"(addr));
}
__device__ __forceinline__ void ldsm4t(uint32_t& r0, uint32_t& r1, uint32_t& r2, uint32_t& r3,
                                       uint32_t addr) {
    asm volatile("ldmatrix.sync.aligned.m8n8.x4.trans.shared.b16 {%0,%1,%2,%3}, [%4];"
                 : "=r"(r0), "=r"(r1), "=r"(r2), "=r"(r3) : "r"(addr));
}

__device__ __forceinline__ float gelu_exact(float v) {
    return 0.5f * v * (1.0f + erff(v * 0.70710678118654752f));
}

// mma.m16n8k16 fp16 -> fp32, row.col
__device__ __forceinline__ void mma16816(float* c, const uint32_t* a, const uint32_t* b) {
    asm volatile(
        "mma.sync.aligned.m16n8k16.row.col.f32.f16.f16.f32 "
        "{%0,%1,%2,%3}, {%4,%5,%6,%7}, {%8,%9}, {%0,%1,%2,%3};"
        : "+f"(c[0]), "+f"(c[1]), "+f"(c[2]), "+f"(c[3])
        : "r"(a[0]), "r"(a[1]), "r"(a[2]), "r"(a[3]), "r"(b[0]), "r"(b[1]));
}
__device__ __forceinline__ uint32_t pack_h2(float x, float y) {
    __half2 h = __floats2half2_rn(x, y);
    return *(uint32_t*)&h;
}

// ---------------- fused float -> half convert (4 arrays, grid.y selects) ----
__global__ void f2h4_kernel(const float4* s0, __half2* d0, int n0,
                            const float4* s1, __half2* d1, int n1,
                            const float4* s2, __half2* d2, int n2,
                            const float4* s3, __half2* d3, int n3) {
    const float4* src; __half2* dst; int n4;
    switch (blockIdx.y) {
        case 0: src = s0; dst = d0; n4 = n0; break;
        case 1: src = s1; dst = d1; n4 = n1; break;
        case 2: src = s2; dst = d2; n4 = n2; break;
        default: src = s3; dst = d3; n4 = n3; break;
    }
    int half_n = n4 >> 1;
    int i = blockIdx.x * blockDim.x + threadIdx.x;
    if (i < half_n) {
        float4 v0 = src[i];
        float4 v1 = src[i + half_n];
        dst[2 * i]     = __floats2half2_rn(v0.x, v0.y);
        dst[2 * i + 1] = __floats2half2_rn(v0.z, v0.w);
        dst[2 * (i + half_n)]     = __floats2half2_rn(v1.x, v1.y);
        dst[2 * (i + half_n) + 1] = __floats2half2_rn(v1.z, v1.w);
    }
}

// ---------------- LayerNorm (fp32 in, half out) -----------------------------
__global__ void ln_kernel(const float* __restrict__ x,
                          const float* __restrict__ w,
                          const float* __restrict__ b,
                          __half* __restrict__ out) {
    int row = blockIdx.x;
    int tid = threadIdx.x;
    const float* xr = x + (size_t)row * DMODEL;

    float4 v = *(const float4*)(xr + tid * 4);
    float s  = v.x + v.y + v.z + v.w;
    float ss = v.x * v.x + v.y * v.y + v.z * v.z + v.w * v.w;

    #pragma unroll
    for (int off = 16; off >= 1; off >>= 1) {
        s  += __shfl_xor_sync(0xffffffffu, s,  off);
        ss += __shfl_xor_sync(0xffffffffu, ss, off);
    }
    __shared__ float rs[8], rss[8];
    __shared__ float stats[2];
    int wid = tid >> 5, lane = tid & 31;
    if (lane == 0) { rs[wid] = s; rss[wid] = ss; }
    __syncthreads();
    if (tid == 0) {
        float S = 0.f, SS = 0.f;
        #pragma unroll
        for (int i = 0; i < 8; i++) { S += rs[i]; SS += rss[i]; }
        float mu  = S * (1.0f / DMODEL);
        float var = SS * (1.0f / DMODEL) - mu * mu;
        stats[0] = mu;
        stats[1] = rsqrtf(var + 1e-5f);
    }
    __syncthreads();
    float mu = stats[0], r = stats[1];

    float4 wv = *(const float4*)(w + tid * 4);
    float4 bv = *(const float4*)(b + tid * 4);
    float o0 = (v.x - mu) * r * wv.x + bv.x;
    float o1 = (v.y - mu) * r * wv.y + bv.y;
    float o2 = (v.z - mu) * r * wv.z + bv.z;
    float o3 = (v.w - mu) * r * wv.w + bv.w;
    __half2* orow = (__half2*)(out + (size_t)row * DMODEL);
    orow[tid * 2]     = __floats2half2_rn(o0, o1);
    orow[tid * 2 + 1] = __floats2half2_rn(o2, o3);
}

// ---------------- fp16 GEMM NT: ldmatrix + mma, swizzled smem ----------------
// (frozen — at the legacy-HMMA ceiling)
#define GK 64
#define NSTG 3
#define TILE_H (128 * 64)
#define STG_B (2 * TILE_H * 2)
#define GEMM_SMEM (NSTG * STG_B)          // 98304 bytes

__device__ __forceinline__ uint32_t swz(int row, int ch) {
    return (uint32_t)(row * 64 + ((ch ^ (row & 7)) * 8));
}

template <int EPI, int HOUT>
__global__ void __launch_bounds__(256, 2)
gemm_h(const __half* __restrict__ A, const __half* __restrict__ B,
       const float* __restrict__ bias, const float* __restrict__ res,
       float* __restrict__ C, __half* __restrict__ Ch, int N, int K) {
    extern __shared__ __align__(16) __half sm[];
    uint32_t sb = smem_u32(sm);

    int tid = threadIdx.x;
    int wid = tid >> 5, lane = tid & 31;
    int g = lane >> 2, t = lane & 3;
    int bn = blockIdx.x, bm = blockIdx.y;
    int wm = wid & 3;
    int wn = wid >> 2;
    const int KT = K / GK;

    float acc[2][8][4];
    #pragma unroll
    for (int mt = 0; mt < 2; mt++)
        #pragma unroll
        for (int n = 0; n < 8; n++)
            #pragma unroll
            for (int i = 0; i < 4; i++) acc[mt][n][i] = 0.f;

    const __half* Ab = A + (size_t)(bm * 128) * K;
    const __half* Bb = B + (size_t)(bn * 128) * K;

    auto issue = [&](int kt) {
        uint32_t dst = sb + (uint32_t)(kt % NSTG) * STG_B;
        #pragma unroll
        for (int i = 0; i < 4; i++) {
            int c = i * 256 + tid;
            int row = c >> 3, ch = c & 7;
            cpa16(dst + swz(row, ch) * 2,              Ab + (size_t)row * K + kt * GK + ch * 8);
            cpa16(dst + TILE_H * 2 + swz(row, ch) * 2, Bb + (size_t)row * K + kt * GK + ch * 8);
        }
    };

    issue(0); cp_commit();
    issue(1); cp_commit();

    for (int kt = 0; kt < KT; kt++) {
        bool more = (kt + 2 < KT);
        if (more) cp_wait<1>();
        else      cp_wait<0>();
        __syncthreads();
        if (more) { issue(kt + 2); cp_commit(); }

        uint32_t stA = sb + (uint32_t)(kt % NSTG) * STG_B;
        uint32_t stB = stA + TILE_H * 2;

        #pragma unroll
        for (int kk = 0; kk < 4; kk++) {
            uint32_t a[2][4];
            #pragma unroll
            for (int mt = 0; mt < 2; mt++) {
                int row = wm * 32 + mt * 16 + (lane & 7) + ((lane >> 3) & 1) * 8;
                int ch  = kk * 2 + (lane >> 4);
                ldsm4(a[mt][0], a[mt][1], a[mt][2], a[mt][3], stA + swz(row, ch) * 2);
            }
            uint32_t bfr[8][2];
            #pragma unroll
            for (int np = 0; np < 4; np++) {
                uint32_t r0, r1, r2, r3;
                int row = wn * 64 + np * 16 + (lane & 7) + ((lane >> 3) & 1) * 8;
                int ch  = kk * 2 + (lane >> 4);
                ldsm4(r0, r1, r2, r3, stB + swz(row, ch) * 2);
                bfr[np * 2][0]     = r0; bfr[np * 2][1]     = r2;
                bfr[np * 2 + 1][0] = r1; bfr[np * 2 + 1][1] = r3;
            }
            #pragma unroll
            for (int mt = 0; mt < 2; mt++)
                #pragma unroll
                for (int n = 0; n < 8; n++)
                    mma16816(acc[mt][n], a[mt], bfr[n]);
        }
    }

    __syncthreads();
    float* Cs = (float*)sm;
    #pragma unroll
    for (int mt = 0; mt < 2; mt++)
        #pragma unroll
        for (int n = 0; n < 8; n++) {
            int r0 = wm * 32 + mt * 16 + g;
            int c0 = wn * 64 + n * 8 + 2 * t;
            Cs[r0 * 132 + c0]           = acc[mt][n][0];
            Cs[r0 * 132 + c0 + 1]       = acc[mt][n][1];
            Cs[(r0 + 8) * 132 + c0]     = acc[mt][n][2];
            Cs[(r0 + 8) * 132 + c0 + 1] = acc[mt][n][3];
        }
    __syncthreads();

    int m0 = bm * 128, n0 = bn * 128;
    #pragma unroll
    for (int it = 0; it < 16; it++) {
        int idx = tid + it * 256;
        int r  = idx >> 5;
        int c4 = (idx & 31) * 4;
        float4 v = *(const float4*)&Cs[r * 132 + c4];
        float4 bv = *(const float4*)(bias + n0 + c4);
        v.x += bv.x; v.y += bv.y; v.z += bv.z; v.w += bv.w;
        if (EPI == 1) {
            v.x = gelu_exact(v.x); v.y = gelu_exact(v.y);
            v.z = gelu_exact(v.z); v.w = gelu_exact(v.w);
        }
        size_t off = (size_t)(m0 + r) * N + n0 + c4;
        if (EPI == 2) {
            float4 rv = *(const float4*)(res + off);
            v.x += rv.x; v.y += rv.y; v.z += rv.z; v.w += rv.w;
        }
        if (HOUT) {
            __half2* hp = (__half2*)(Ch + off);
            hp[0] = __floats2half2_rn(v.x, v.y);
            hp[1] = __floats2half2_rn(v.z, v.w);
        } else {
            *(float4*)(C + off) = v;
        }
    }
}

// ---------------- FA2 fp16 attention (base-2 softmax, longest-first) --------
// grid (T/64, H, B), 4 warps, static smem, K/V double-buffered cp.async.
// qb reversed vs blockIdx.x: longest CTAs dispatch first (LPT scheduling).
#define ATS 72    // smem stride in halves

__global__ void __launch_bounds__(128)
attn_h(const __half* __restrict__ qkv, __half* __restrict__ y) {
    __shared__ __align__(16) __half Qs[64 * ATS];
    __shared__ __align__(16) __half KV[2][2][64 * ATS];   // [stage][K/V][row][col]

    int qb = gridDim.x - 1 - blockIdx.x;   // longest-first dispatch
    int h = blockIdx.y, b = blockIdx.z;
    int tid = threadIdx.x;
    int w = tid >> 5, lane = tid & 31;
    int g = lane >> 2, t = lane & 3;
    size_t base = (size_t)b * TSEQ * D3;
    int hoff = h * DHEAD;

    uint32_t sbKV = smem_u32(&KV[0][0][0]);

    auto loadKV = [&](int kb, int st) {
        #pragma unroll
        for (int i = 0; i < 8; i++) {
            int idx = tid + i * 128;            // 0..1023
            int isV = idx >> 9;
            int row = (idx >> 3) & 63;
            int ch  = idx & 7;
            const __half* src = qkv + base + (size_t)(kb * 64 + row) * D3 + hoff
                               + 1024 + isV * 1024 + ch * 8;
            cpa16(sbKV + (uint32_t)(((st * 2 + isV) * 64 + row) * ATS + ch * 8) * 2, src);
        }
    };

    // load Q tile + prefetch KV(0)
    #pragma unroll
    for (int i = 0; i < 16; i++) {
        int idx = tid + i * 128;
        int row = idx >> 5, c2 = idx & 31;
        *(__half2*)&Qs[row * ATS + c2 * 2] =
            *(const __half2*)(qkv + base + (size_t)(qb * 64 + row) * D3 + hoff + c2 * 2);
    }
    loadKV(0, 0); cp_commit();
    __syncthreads();

    // Q fragments, pre-scaled by log2(e)/8 (base-2 softmax domain)
    uint32_t qf[4][4];
    const __half2 hsc = __floats2half2_rn(0.18033688f, 0.18033688f);
    #pragma unroll
    for (int kc = 0; kc < 4; kc++) {
        int row = w * 16 + (lane & 7) + ((lane >> 3) & 1) * 8;
        int col = kc * 16 + (lane >> 4) * 8;
        ldsm4(qf[kc][0], qf[kc][1], qf[kc][2], qf[kc][3],
              smem_u32(&Qs[row * ATS + col]));
        #pragma unroll
        for (int i = 0; i < 4; i++) {
            __half2 v = __hmul2(*(__half2*)&qf[kc][i], hsc);
            qf[kc][i] = *(uint32_t*)&v;
        }
    }

    float o[8][4];
    #pragma unroll
    for (int n = 0; n < 8; n++)
        #pragma unroll
        for (int i = 0; i < 4; i++) o[n][i] = 0.f;
    float m0r = -INFINITY, m1r = -INFINITY, l0r = 0.f, l1r = 0.f;

    int rowq0 = qb * 64 + w * 16 + g;
    int rowq1 = rowq0 + 8;

    for (int kb = 0; kb <= qb; kb++) {
        int st = kb & 1;
        if (kb < qb) { loadKV(kb + 1, st ^ 1); cp_commit(); cp_wait<1>(); }
        else         { cp_wait<0>(); }
        __syncthreads();

        uint32_t stK = sbKV + (uint32_t)((st * 2) * 64 * ATS) * 2;
        uint32_t stV = sbKV + (uint32_t)((st * 2 + 1) * 64 * ATS) * 2;

        // ---- S2 = (Q*log2e/8) K^T  (log2 domain) ----
        float c[8][4];
        #pragma unroll
        for (int n = 0; n < 8; n++)
            #pragma unroll
            for (int i = 0; i < 4; i++) c[n][i] = 0.f;

        #pragma unroll
        for (int kc = 0; kc < 4; kc++) {
            #pragma unroll
            for (int n16 = 0; n16 < 4; n16++) {
                uint32_t r0, r1, r2, r3;
                int row = n16 * 16 + (lane & 7) + ((lane >> 3) & 1) * 8;
                int col = kc * 16 + (lane >> 4) * 8;
                ldsm4(r0, r1, r2, r3, stK + (uint32_t)(row * ATS + col) * 2);
                uint32_t b0[2] = {r0, r2}, b1[2] = {r1, r3};
                mma16816(c[2 * n16],     qf[kc], b0);
                mma16816(c[2 * n16 + 1], qf[kc], b1);
            }
        }

        // ---- online softmax, base 2 ----
        float smax0 = -1e30f, smax1 = -1e30f;
        #pragma unroll
        for (int n = 0; n < 8; n++) {
            int col = kb * 64 + n * 8 + 2 * t;
            if (kb == qb) {
                if (col     > rowq0) c[n][0] = -1e30f;
                if (col + 1 > rowq0) c[n][1] = -1e30f;
                if (col     > rowq1) c[n][2] = -1e30f;
                if (col + 1 > rowq1) c[n][3] = -1e30f;
            }
            smax0 = fmaxf(smax0, fmaxf(c[n][0], c[n][1]));
            smax1 = fmaxf(smax1, fmaxf(c[n][2], c[n][3]));
        }
        smax0 = fmaxf(smax0, __shfl_xor_sync(0xffffffffu, smax0, 1));
        smax0 = fmaxf(smax0, __shfl_xor_sync(0xffffffffu, smax0, 2));
        smax1 = fmaxf(smax1, __shfl_xor_sync(0xffffffffu, smax1, 1));
        smax1 = fmaxf(smax1, __shfl_xor_sync(0xffffffffu, smax1, 2));

        float mn0 = fmaxf(m0r, smax0), mn1 = fmaxf(m1r, smax1);
        float f0 = exp2f(m0r - mn0),  f1 = exp2f(m1r - mn1);
        m0r = mn0; m1r = mn1;

        float s0 = 0.f, s1 = 0.f;
        #pragma unroll
        for (int n = 0; n < 8; n++) {
            c[n][0] = exp2f(c[n][0] - mn0); c[n][1] = exp2f(c[n][1] - mn0);
            c[n][2] = exp2f(c[n][2] - mn1); c[n][3] = exp2f(c[n][3] - mn1);
            s0 += c[n][0] + c[n][1];
            s1 += c[n][2] + c[n][3];
        }
        s0 += __shfl_xor_sync(0xffffffffu, s0, 1);
        s0 += __shfl_xor_sync(0xffffffffu, s0, 2);
        s1 += __shfl_xor_sync(0xffffffffu, s1, 1);
        s1 += __shfl_xor_sync(0xffffffffu, s1, 2);
        l0r = l0r * f0 + s0;
        l1r = l1r * f1 + s1;

        #pragma unroll
        for (int n = 0; n < 8; n++) {
            o[n][0] *= f0; o[n][1] *= f0;
            o[n][2] *= f1; o[n][3] *= f1;
        }

        // ---- O += P V : V B-frags via ldmatrix.trans ----
        #pragma unroll
        for (int kc = 0; kc < 4; kc++) {
            uint32_t pa[4];
            pa[0] = pack_h2(c[2 * kc][0],     c[2 * kc][1]);
            pa[1] = pack_h2(c[2 * kc][2],     c[2 * kc][3]);
            pa[2] = pack_h2(c[2 * kc + 1][0], c[2 * kc + 1][1]);
            pa[3] = pack_h2(c[2 * kc + 1][2], c[2 * kc + 1][3]);
            #pragma unroll
            for (int d16 = 0; d16 < 4; d16++) {
                uint32_t r0, r1, r2, r3;
                int m = lane >> 3;
                int row = kc * 16 + (m & 1) * 8 + (lane & 7);
                int col = d16 * 16 + (m >> 1) * 8;
                ldsm4t(r0, r1, r2, r3, stV + (uint32_t)(row * ATS + col) * 2);
                uint32_t b0[2] = {r0, r1}, b1[2] = {r2, r3};
                mma16816(o[2 * d16],     pa, b0);
                mma16816(o[2 * d16 + 1], pa, b1);
            }
        }
        __syncthreads();
    }

    // ---- epilogue ----
    float inv0 = 1.0f / l0r, inv1 = 1.0f / l1r;
    size_t r0 = (size_t)(b * TSEQ + qb * 64 + w * 16 + g) * DMODEL + hoff;
    size_t r1 = r0 + (size_t)8 * DMODEL;
    #pragma unroll
    for (int n = 0; n < 8; n++) {
        int col = n * 8 + 2 * t;
        *(__half2*)(y + r0 + col) = __floats2half2_rn(o[n][0] * inv0, o[n][1] * inv0);
        *(__half2*)(y + r1 + col) = __floats2half2_rn(o[n][2] * inv1, o[n][3] * inv1);
    }
}

// ---------------- launch ----------------------------------------------------
template <typename T>
static T* symaddr(const void* sym) {
    void* p = nullptr;
    cudaGetSymbolAddress(&p, sym);
    return (T*)p;
}

extern "C" void kernel_launch(void* const* d_in, const int* in_sizes, int n_in,
                              void* d_out, int out_size) {
    const float* x      = (const float*)d_in[0];
    const float* ln1_w  = (const float*)d_in[1];
    const float* ln1_b  = (const float*)d_in[2];
    const float* qkv_w  = (const float*)d_in[3];
    const float* qkv_b  = (const float*)d_in[4];
    const float* out_w  = (const float*)d_in[5];
    const float* out_b  = (const float*)d_in[6];
    const float* ln2_w  = (const float*)d_in[7];
    const float* ln2_b  = (const float*)d_in[8];
    const float* mlp_w1 = (const float*)d_in[9];
    const float* mlp_b1 = (const float*)d_in[10];
    const float* mlp_w2 = (const float*)d_in[11];
    const float* mlp_b2 = (const float*)d_in[12];
    float* out = (float*)d_out;

    float*  x1   = symaddr<float>(g_x1);
    __half* qkvh = symaddr<__half>(g_qkv_h);
    __half* xlnh = symaddr<__half>(g_xln_h);
    __half* yh   = symaddr<__half>(g_y_h);
    __half* hh   = symaddr<__half>(g_h_h);
    __half* acth = symaddr<__half>(g_act_h);
    __half* wqh  = symaddr<__half>(g_wq_h);
    __half* woh  = symaddr<__half>(g_wo_h);
    __half* w1h  = symaddr<__half>(g_w1_h);
    __half* w2h  = symaddr<__half>(g_w2_h);

    cudaFuncSetAttribute(gemm_h<0,1>, cudaFuncAttributeMaxDynamicSharedMemorySize, GEMM_SMEM);
    cudaFuncSetAttribute(gemm_h<1,1>, cudaFuncAttributeMaxDynamicSharedMemorySize, GEMM_SMEM);
    cudaFuncSetAttribute(gemm_h<2,0>, cudaFuncAttributeMaxDynamicSharedMemorySize, GEMM_SMEM);

    // 0. weights -> half (single fused launch)
    {
        int n_wq = D3 * DMODEL / 4, n_wo = DMODEL * DMODEL / 4;
        int n_w1 = DFF * DMODEL / 4, n_w2 = DMODEL * DFF / 4;
        int maxb = (n_w1 / 2 + 255) / 256;
        f2h4_kernel<<<dim3(maxb, 4), 256>>>(
            (const float4*)qkv_w, (__half2*)wqh, n_wq,
            (const float4*)out_w, (__half2*)woh, n_wo,
            (const float4*)mlp_w1, (__half2*)w1h, n_w1,
            (const float4*)mlp_w2, (__half2*)w2h, n_w2);
    }

    // 1. LN1 -> half
    ln_kernel<<<MROWS, 256>>>(x, ln1_w, ln1_b, xlnh);
    // 2. QKV projection -> half qkv
    gemm_h<0,1><<<dim3(D3 / 128, MROWS / 128), 256, GEMM_SMEM>>>(xlnh, wqh, qkv_b, nullptr, nullptr, qkvh, D3, DMODEL);
    // 3. causal attention (fp16 mma, base-2 softmax, longest-first) -> half y
    attn_h<<<dim3(TSEQ / 64, NHEAD, 2), 128>>>(qkvh, yh);
    // 4. out projection + residual -> fp32 x1
    gemm_h<2,0><<<dim3(DMODEL / 128, MROWS / 128), 256, GEMM_SMEM>>>(yh, woh, out_b, x, x1, nullptr, DMODEL, DMODEL);
    // 5. LN2 -> half
    ln_kernel<<<MROWS, 256>>>(x1, ln2_w, ln2_b, hh);
    // 6. MLP up + exact GELU -> half act
    gemm_h<1,1><<<dim3(DFF / 128, MROWS / 128), 256, GEMM_SMEM>>>(hh, w1h, mlp_b1, nullptr, nullptr, acth, DFF, DMODEL);
    // 7. MLP down + residual -> fp32 output
    gemm_h<2,0><<<dim3(DMODEL / 128, MROWS / 128), 256, GEMM_SMEM>>>(acth, w2h, mlp_b2, x1, out, nullptr, DMODEL, DFF);
}